// round 1
// baseline (speedup 1.0000x reference)
#include <cuda_runtime.h>
#include <cstdint>

// ---------------------------------------------------------------------------
// EarthAttention3D (Pangu-style windowed attention)
//   DIM=192, HEADS=6, HD=32, T=144 tokens/window, NW=960 windows
//   pipeline: qkv = x@Wqkv+b  ->  per-(window,head) attention  ->  out = a@Wout+b
// ---------------------------------------------------------------------------

constexpr int TOK   = 144;
constexpr int NHEAD = 6;
constexpr int HD    = 32;
constexpr int DIM   = 192;
constexpr int NWIN  = 960;
constexpr int NWW   = 15;   // windows along w
constexpr int NWH   = 16;   // windows along h (broadcast axis for bias)
constexpr float QSCALE = 0.17677669529663687f; // 32^-0.5

// scratch (device globals: allocation-free)
__device__ float g_qkv[(size_t)NWIN * 3 * NHEAD * TOK * HD]; // [b][s][h][t][d]
__device__ float g_att[(size_t)NWIN * TOK * DIM];            // [b][t][h*32+d]

// ---------------------------------------------------------------------------
// GEMM 1: qkv = x[138240,192] @ Wqkv[192,576] + b ; scatter into g_qkv
// 64x64 block tile, BK=16, 256 threads, 4x4 per thread
// ---------------------------------------------------------------------------
__global__ void __launch_bounds__(256) qkv_gemm_kernel(
    const float* __restrict__ x, const float* __restrict__ Wqkv,
    const float* __restrict__ bqkv)
{
    constexpr int N = 576, K = DIM;
    __shared__ float As[16][65];   // [k][m] transposed
    __shared__ float Bs[16][64];   // [k][n]

    const int tid = threadIdx.x;
    const int tx = tid & 15, ty = tid >> 4;
    const int m0 = blockIdx.x * 64;
    const int n0 = blockIdx.y * 64;

    const int arow  = tid >> 2;        // 0..63
    const int acol4 = (tid & 3) * 4;   // 0,4,8,12
    const int brow  = tid >> 4;        // 0..15
    const int bcol4 = (tid & 15) * 4;  // 0..60

    float acc[4][4] = {};

    for (int k0 = 0; k0 < K; k0 += 16) {
        float4 av = *reinterpret_cast<const float4*>(
            &x[(size_t)(m0 + arow) * K + k0 + acol4]);
        As[acol4 + 0][arow] = av.x;
        As[acol4 + 1][arow] = av.y;
        As[acol4 + 2][arow] = av.z;
        As[acol4 + 3][arow] = av.w;
        *reinterpret_cast<float4*>(&Bs[brow][bcol4]) =
            *reinterpret_cast<const float4*>(&Wqkv[(size_t)(k0 + brow) * N + n0 + bcol4]);
        __syncthreads();
        #pragma unroll
        for (int k = 0; k < 16; k++) {
            float a[4];
            #pragma unroll
            for (int i = 0; i < 4; i++) a[i] = As[k][ty * 4 + i];
            float4 b4 = *reinterpret_cast<float4*>(&Bs[k][tx * 4]);
            float b[4] = {b4.x, b4.y, b4.z, b4.w};
            #pragma unroll
            for (int i = 0; i < 4; i++)
                #pragma unroll
                for (int j = 0; j < 4; j++)
                    acc[i][j] += a[i] * b[j];
        }
        __syncthreads();
    }

    // epilogue: bias, q-scale, scatter to [b][s][h][t][d]
    #pragma unroll
    for (int i = 0; i < 4; i++) {
        const int m = m0 + ty * 4 + i;
        const int b = m / TOK, t = m % TOK;
        #pragma unroll
        for (int j = 0; j < 4; j++) {
            const int n = n0 + tx * 4 + j;
            float v = acc[i][j] + bqkv[n];
            const int s   = n / DIM;
            const int rem = n - s * DIM;
            const int h   = rem >> 5;
            const int d   = rem & 31;
            if (s == 0) v *= QSCALE;
            g_qkv[((((size_t)b * 3 + s) * NHEAD + h) * TOK + t) * HD + d] = v;
        }
    }
}

// ---------------------------------------------------------------------------
// Attention: one block per (window b, head h). grid (960, 6), 256 threads.
// SMEM: q/k/v [144][33] + S [144][145] + rinv[144]
// ---------------------------------------------------------------------------
__global__ void __launch_bounds__(256) attn_kernel(
    const float* __restrict__ mask, const float* __restrict__ bias_table)
{
    extern __shared__ float smem[];
    float* qs   = smem;                 // 144*33
    float* ks   = qs + TOK * 33;
    float* vs   = ks + TOK * 33;
    float* Ss   = vs + TOK * 33;        // 144*145
    float* rinv = Ss + TOK * 145;       // 144

    const int b = blockIdx.x;
    const int h = blockIdx.y;
    const int tid = threadIdx.x;

    const float* qg = &g_qkv[(((size_t)b * 3 + 0) * NHEAD + h) * TOK * HD];
    const float* kg = &g_qkv[(((size_t)b * 3 + 1) * NHEAD + h) * TOK * HD];
    const float* vg = &g_qkv[(((size_t)b * 3 + 2) * NHEAD + h) * TOK * HD];

    // load q,k,v (144x32 each) into padded smem
    for (int idx = tid; idx < TOK * 8; idx += 256) {
        const int row = idx >> 3;
        const int c4  = (idx & 7) * 4;
        float4 q4 = *reinterpret_cast<const float4*>(qg + row * 32 + c4);
        float4 k4 = *reinterpret_cast<const float4*>(kg + row * 32 + c4);
        float4 v4 = *reinterpret_cast<const float4*>(vg + row * 32 + c4);
        float* qp = &qs[row * 33 + c4];
        qp[0] = q4.x; qp[1] = q4.y; qp[2] = q4.z; qp[3] = q4.w;
        float* kp = &ks[row * 33 + c4];
        kp[0] = k4.x; kp[1] = k4.y; kp[2] = k4.z; kp[3] = k4.w;
        float* vp = &vs[row * 33 + c4];
        vp[0] = v4.x; vp[1] = v4.y; vp[2] = v4.z; vp[3] = v4.w;
    }
    __syncthreads();

    // ---- S = q @ k^T  (9x9 register tile per thread, 16x16 thread grid) ----
    const int tx = tid & 15, ty = tid >> 4;
    float acc[9][9] = {};
    #pragma unroll 4
    for (int d = 0; d < HD; d++) {
        float qa[9], kb[9];
        #pragma unroll
        for (int i = 0; i < 9; i++) qa[i] = qs[(ty * 9 + i) * 33 + d];
        #pragma unroll
        for (int j = 0; j < 9; j++) kb[j] = ks[(tx * 9 + j) * 33 + d];
        #pragma unroll
        for (int i = 0; i < 9; i++)
            #pragma unroll
            for (int j = 0; j < 9; j++)
                acc[i][j] += qa[i] * kb[j];
    }

    // ---- + earth bias + mask, store to Ss ----
    const int wz   = b / (NWH * NWW);
    const int ww   = b % NWW;
    const int nsub = wz * NWW + ww;
    const float* bt   = bias_table + nsub * NHEAD + h;  // + pos*360
    const float* mrow = mask + (size_t)b * TOK * TOK;

    #pragma unroll
    for (int i = 0; i < 9; i++) {
        const int t  = ty * 9 + i;
        const int zt = t / 72;
        const int ht = (t % 72) / 12;
        const int wt = t % 12;
        #pragma unroll
        for (int j = 0; j < 9; j++) {
            const int s  = tx * 9 + j;
            const int zs = s / 72;
            const int hs = (s % 72) / 12;
            const int wd = s % 12;
            const int pos = (zt + zs * 2) * 1584 + (ht - hs + 5) * 144 + (wt + wd * 12);
            Ss[t * 145 + s] = acc[i][j] + bt[(size_t)pos * 360] + mrow[t * 144 + s];
        }
    }
    __syncthreads();

    // ---- softmax per row (warp per row, 8 warps, 18 rows each) ----
    const int lane = tid & 31, wid = tid >> 5;
    for (int t = wid; t < TOK; t += 8) {
        float mx = -1e30f;
        for (int s = lane; s < TOK; s += 32) mx = fmaxf(mx, Ss[t * 145 + s]);
        #pragma unroll
        for (int o = 16; o > 0; o >>= 1) mx = fmaxf(mx, __shfl_xor_sync(~0u, mx, o));
        float sum = 0.f;
        for (int s = lane; s < TOK; s += 32) {
            float e = __expf(Ss[t * 145 + s] - mx);
            Ss[t * 145 + s] = e;
            sum += e;
        }
        #pragma unroll
        for (int o = 16; o > 0; o >>= 1) sum += __shfl_xor_sync(~0u, sum, o);
        if (lane == 0) rinv[t] = 1.0f / sum;
    }
    __syncthreads();

    // ---- out = P @ v (9 rows x 2 cols per thread), normalize with rinv ----
    float oacc[9][2] = {};
    for (int s = 0; s < TOK; s++) {
        const float vv0 = vs[s * 33 + tx * 2];
        const float vv1 = vs[s * 33 + tx * 2 + 1];
        #pragma unroll
        for (int i = 0; i < 9; i++) {
            const float p = Ss[(ty * 9 + i) * 145 + s];
            oacc[i][0] += p * vv0;
            oacc[i][1] += p * vv1;
        }
    }
    float* og = &g_att[(size_t)b * TOK * DIM + h * HD];
    #pragma unroll
    for (int i = 0; i < 9; i++) {
        const int t = ty * 9 + i;
        const float r = rinv[t];
        og[(size_t)t * DIM + tx * 2]     = oacc[i][0] * r;
        og[(size_t)t * DIM + tx * 2 + 1] = oacc[i][1] * r;
    }
}

// ---------------------------------------------------------------------------
// GEMM 2: out = g_att[138240,192] @ Wout[192,192] + b_out
// ---------------------------------------------------------------------------
__global__ void __launch_bounds__(256) out_gemm_kernel(
    const float* __restrict__ Wout, const float* __restrict__ bout,
    float* __restrict__ out)
{
    constexpr int N = DIM, K = DIM;
    __shared__ float As[16][65];
    __shared__ float Bs[16][64];

    const int tid = threadIdx.x;
    const int tx = tid & 15, ty = tid >> 4;
    const int m0 = blockIdx.x * 64;
    const int n0 = blockIdx.y * 64;

    const int arow  = tid >> 2;
    const int acol4 = (tid & 3) * 4;
    const int brow  = tid >> 4;
    const int bcol4 = (tid & 15) * 4;

    float acc[4][4] = {};

    for (int k0 = 0; k0 < K; k0 += 16) {
        float4 av = *reinterpret_cast<const float4*>(
            &g_att[(size_t)(m0 + arow) * K + k0 + acol4]);
        As[acol4 + 0][arow] = av.x;
        As[acol4 + 1][arow] = av.y;
        As[acol4 + 2][arow] = av.z;
        As[acol4 + 3][arow] = av.w;
        *reinterpret_cast<float4*>(&Bs[brow][bcol4]) =
            *reinterpret_cast<const float4*>(&Wout[(size_t)(k0 + brow) * N + n0 + bcol4]);
        __syncthreads();
        #pragma unroll
        for (int k = 0; k < 16; k++) {
            float a[4];
            #pragma unroll
            for (int i = 0; i < 4; i++) a[i] = As[k][ty * 4 + i];
            float4 b4 = *reinterpret_cast<float4*>(&Bs[k][tx * 4]);
            float bb[4] = {b4.x, b4.y, b4.z, b4.w};
            #pragma unroll
            for (int i = 0; i < 4; i++)
                #pragma unroll
                for (int j = 0; j < 4; j++)
                    acc[i][j] += a[i] * bb[j];
        }
        __syncthreads();
    }

    #pragma unroll
    for (int i = 0; i < 4; i++) {
        const int m = m0 + ty * 4 + i;
        #pragma unroll
        for (int j = 0; j < 4; j++) {
            const int n = n0 + tx * 4 + j;
            out[(size_t)m * N + n] = acc[i][j] + bout[n];
        }
    }
}

// ---------------------------------------------------------------------------
extern "C" void kernel_launch(void* const* d_in, const int* in_sizes, int n_in,
                              void* d_out, int out_size)
{
    const float* x     = (const float*)d_in[0];
    const float* mask  = (const float*)d_in[1];
    const float* Wqkv  = (const float*)d_in[2];
    const float* bqkv  = (const float*)d_in[3];
    const float* Wout  = (const float*)d_in[4];
    const float* bout  = (const float*)d_in[5];
    const float* bias  = (const float*)d_in[6];
    float* out = (float*)d_out;

    // GEMM1: M=138240 -> 2160 tiles, N=576 -> 9 tiles
    qkv_gemm_kernel<<<dim3(2160, 9), 256>>>(x, Wqkv, bqkv);

    // attention: smem = (3*144*33 + 144*145 + 144) floats
    const size_t shmem = (size_t)(3 * TOK * 33 + TOK * 145 + TOK) * sizeof(float);
    cudaFuncSetAttribute(attn_kernel, cudaFuncAttributeMaxDynamicSharedMemorySize,
                         (int)shmem);
    attn_kernel<<<dim3(NWIN, NHEAD), 256, shmem>>>(mask, bias);

    // GEMM2: M=138240 -> 2160 tiles, N=192 -> 3 tiles
    out_gemm_kernel<<<dim3(2160, 3), 256>>>(Wout, bout, out);
}

// round 2
// speedup vs baseline: 1.6737x; 1.6737x over previous
#include <cuda_runtime.h>
#include <cstdint>

// ---------------------------------------------------------------------------
// EarthAttention3D: qkv GEMM -> per-(window,head) attention -> out GEMM
// DIM=192, HEADS=6, HD=32, T=144, NW=960
// ---------------------------------------------------------------------------

constexpr int TOK   = 144;
constexpr int NHEAD = 6;
constexpr int HD    = 32;
constexpr int DIM   = 192;
constexpr int NWIN  = 960;
constexpr int NWW   = 15;
constexpr int NSUB  = 60;   // NWZ * NWW
constexpr float QSCALE = 0.17677669529663687f;

// scratch (device globals: allocation-free)
__device__ float g_qkv[(size_t)NWIN * 3 * NHEAD * TOK * HD];   // [b][s][h][t][d]
__device__ float g_att[(size_t)NWIN * TOK * DIM];              // [b][t][h*32+d]
__device__ float g_bias[(size_t)NSUB * NHEAD * TOK * TOK];     // [nsub][h][t][s]

// ---------------------------------------------------------------------------
// bias precompute: g_bias[nsub][h][t][s] = bias_table[pos(t,s)*360 + nsub*6 + h]
// ---------------------------------------------------------------------------
__global__ void __launch_bounds__(256) bias_pre_kernel(
    const float* __restrict__ bias_table)
{
    const int idx = blockIdx.x * 256 + threadIdx.x;  // [0, 60*6*144*144)
    const int s    = idx % TOK;
    const int t    = (idx / TOK) % TOK;
    const int h    = (idx / (TOK * TOK)) % NHEAD;
    const int nsub = idx / (TOK * TOK * NHEAD);

    const int zt = t / 72, ht = (t % 72) / 12, wt = t % 12;
    const int zs = s / 72, hs = (s % 72) / 12, wd = s % 12;
    const int pos = (zt + zs * 2) * 1584 + (ht - hs + 5) * 144 + (wt + wd * 12);

    g_bias[idx] = bias_table[(size_t)pos * (NSUB * NHEAD) + nsub * NHEAD + h];
}

// ---------------------------------------------------------------------------
// GEMM 1: qkv = x[138240,192] @ Wqkv[192,576] + b ; scatter into g_qkv
// 128x64 tile, BK=16, 256 threads, 8x4 per thread, all float4 smem access
// ---------------------------------------------------------------------------
__global__ void __launch_bounds__(256) qkv_gemm_kernel(
    const float* __restrict__ x, const float* __restrict__ Wqkv,
    const float* __restrict__ bqkv)
{
    constexpr int N = 576, K = DIM;
    __shared__ float As[16][132];   // [k][m], stride 132 (16B aligned rows)
    __shared__ float Bs[16][64];    // [k][n]

    const int tid = threadIdx.x;
    const int tx = tid & 15, ty = tid >> 4;
    const int m0 = blockIdx.x * 128;
    const int n0 = blockIdx.y * 64;

    const int ar  = tid >> 2;        // 0..63
    const int ac4 = (tid & 3) * 4;   // 0,4,8,12
    const int br  = tid >> 4;        // 0..15
    const int bc4 = (tid & 15) * 4;  // 0..60

    float acc[8][4] = {};

    for (int k0 = 0; k0 < K; k0 += 16) {
        float4 a0 = *reinterpret_cast<const float4*>(
            &x[(size_t)(m0 + ar) * K + k0 + ac4]);
        float4 a1 = *reinterpret_cast<const float4*>(
            &x[(size_t)(m0 + ar + 64) * K + k0 + ac4]);
        As[ac4 + 0][ar] = a0.x; As[ac4 + 1][ar] = a0.y;
        As[ac4 + 2][ar] = a0.z; As[ac4 + 3][ar] = a0.w;
        As[ac4 + 0][ar + 64] = a1.x; As[ac4 + 1][ar + 64] = a1.y;
        As[ac4 + 2][ar + 64] = a1.z; As[ac4 + 3][ar + 64] = a1.w;
        *reinterpret_cast<float4*>(&Bs[br][bc4]) =
            *reinterpret_cast<const float4*>(&Wqkv[(size_t)(k0 + br) * N + n0 + bc4]);
        __syncthreads();
        #pragma unroll
        for (int k = 0; k < 16; k++) {
            float4 a04 = *reinterpret_cast<float4*>(&As[k][ty * 8]);
            float4 a14 = *reinterpret_cast<float4*>(&As[k][ty * 8 + 4]);
            float4 b4  = *reinterpret_cast<float4*>(&Bs[k][tx * 4]);
            float am[8] = {a04.x, a04.y, a04.z, a04.w, a14.x, a14.y, a14.z, a14.w};
            float bn[4] = {b4.x, b4.y, b4.z, b4.w};
            #pragma unroll
            for (int i = 0; i < 8; i++)
                #pragma unroll
                for (int j = 0; j < 4; j++)
                    acc[i][j] += am[i] * bn[j];
        }
        __syncthreads();
    }

    // epilogue: bias, q-scale, scatter; each (i) row is one float4 into g_qkv
    const int n = n0 + tx * 4;           // multiple of 4
    const int s = n / DIM;
    const int h = (n % DIM) >> 5;
    const int d = n & 31;                // 4-aligned, same h for j=0..3
    float bj[4];
    #pragma unroll
    for (int j = 0; j < 4; j++) bj[j] = bqkv[n + j];
    const float sc = (s == 0) ? QSCALE : 1.0f;

    #pragma unroll
    for (int i = 0; i < 8; i++) {
        const int m = m0 + ty * 8 + i;
        const int b = m / TOK, t = m % TOK;
        float4 v;
        v.x = (acc[i][0] + bj[0]) * sc;
        v.y = (acc[i][1] + bj[1]) * sc;
        v.z = (acc[i][2] + bj[2]) * sc;
        v.w = (acc[i][3] + bj[3]) * sc;
        *reinterpret_cast<float4*>(
            &g_qkv[((((size_t)b * 3 + s) * NHEAD + h) * TOK + t) * HD + d]) = v;
    }
}

// ---------------------------------------------------------------------------
// Attention: block per (head h, window b). grid (6, 960), 256 threads.
// register softmax via width-16 shuffles; P staged in smem only for PV.
// ---------------------------------------------------------------------------
__global__ void __launch_bounds__(256) attn_kernel(const float* __restrict__ mask)
{
    extern __shared__ float smem[];
    float* vs = smem;                   // 144*36
    float* qs = vs + TOK * 36;
    float* ks = qs + TOK * 36;
    float* Ss = ks + TOK * 36;          // 144*148

    const int h = blockIdx.x;
    const int b = blockIdx.y;
    const int tid = threadIdx.x;

    const float* qg = &g_qkv[(((size_t)b * 3 + 0) * NHEAD + h) * TOK * HD];
    const float* kg = &g_qkv[(((size_t)b * 3 + 1) * NHEAD + h) * TOK * HD];
    const float* vg = &g_qkv[(((size_t)b * 3 + 2) * NHEAD + h) * TOK * HD];

    for (int idx = tid; idx < TOK * 8; idx += 256) {
        const int row = idx >> 3;
        const int c4  = (idx & 7) * 4;
        *reinterpret_cast<float4*>(&qs[row * 36 + c4]) =
            *reinterpret_cast<const float4*>(qg + row * 32 + c4);
        *reinterpret_cast<float4*>(&ks[row * 36 + c4]) =
            *reinterpret_cast<const float4*>(kg + row * 32 + c4);
        *reinterpret_cast<float4*>(&vs[row * 36 + c4]) =
            *reinterpret_cast<const float4*>(vg + row * 32 + c4);
    }
    __syncthreads();

    const int tx = tid & 15, ty = tid >> 4;
    const int t0 = ty * 9, s0 = tx * 9;

    // ---- S = q @ k^T (9x9 regs, float4 over d) ----
    float acc[9][9] = {};
    #pragma unroll
    for (int d4 = 0; d4 < HD; d4 += 4) {
        float4 qa[9];
        #pragma unroll
        for (int i = 0; i < 9; i++)
            qa[i] = *reinterpret_cast<const float4*>(&qs[(t0 + i) * 36 + d4]);
        #pragma unroll
        for (int j = 0; j < 9; j++) {
            float4 kb = *reinterpret_cast<const float4*>(&ks[(s0 + j) * 36 + d4]);
            #pragma unroll
            for (int i = 0; i < 9; i++) {
                acc[i][j] += qa[i].x * kb.x + qa[i].y * kb.y
                           + qa[i].z * kb.z + qa[i].w * kb.w;
            }
        }
    }

    // ---- + bias + mask, register softmax (rows live in half-warps) ----
    const int wz = b / 240, ww = b % NWW;
    const int nsub = wz * NWW + ww;
    const float* pb = g_bias + ((size_t)(nsub * NHEAD + h) * TOK) * TOK;
    const float* mk = mask + (size_t)b * TOK * TOK;

    float rinv[9];
    #pragma unroll
    for (int i = 0; i < 9; i++) {
        const int t = t0 + i;
        const float* pbr = pb + t * TOK + s0;
        const float* mkr = mk + t * TOK + s0;
        float mx = -1e30f;
        #pragma unroll
        for (int j = 0; j < 9; j++) {
            acc[i][j] += pbr[j] + mkr[j];
            mx = fmaxf(mx, acc[i][j]);
        }
        #pragma unroll
        for (int o = 8; o; o >>= 1)
            mx = fmaxf(mx, __shfl_xor_sync(0xffffffffu, mx, o, 16));
        float sum = 0.f;
        #pragma unroll
        for (int j = 0; j < 9; j++) {
            float e = __expf(acc[i][j] - mx);
            acc[i][j] = e;
            sum += e;
        }
        #pragma unroll
        for (int o = 8; o; o >>= 1)
            sum += __shfl_xor_sync(0xffffffffu, sum, o, 16);
        rinv[i] = 1.0f / sum;
        float* sr = &Ss[t * 148 + s0];
        #pragma unroll
        for (int j = 0; j < 9; j++) sr[j] = acc[i][j];
    }
    __syncthreads();

    // ---- out = P @ v : 9 rows x 2 cols, float4 P / float2 V ----
    float oa[9][2] = {};
    const int d0 = tx * 2;
    #pragma unroll 2
    for (int s4 = 0; s4 < TOK; s4 += 4) {
        float2 vv[4];
        #pragma unroll
        for (int q = 0; q < 4; q++)
            vv[q] = *reinterpret_cast<const float2*>(&vs[(s4 + q) * 36 + d0]);
        #pragma unroll
        for (int i = 0; i < 9; i++) {
            float4 p = *reinterpret_cast<const float4*>(&Ss[(t0 + i) * 148 + s4]);
            oa[i][0] += p.x * vv[0].x + p.y * vv[1].x + p.z * vv[2].x + p.w * vv[3].x;
            oa[i][1] += p.x * vv[0].y + p.y * vv[1].y + p.z * vv[2].y + p.w * vv[3].y;
        }
    }
    float* og = g_att + (size_t)b * TOK * DIM + h * HD + d0;
    #pragma unroll
    for (int i = 0; i < 9; i++) {
        float2 o2 = make_float2(oa[i][0] * rinv[i], oa[i][1] * rinv[i]);
        *reinterpret_cast<float2*>(&og[(size_t)(t0 + i) * DIM]) = o2;
    }
}

// ---------------------------------------------------------------------------
// GEMM 2: out = g_att[138240,192] @ Wout[192,192] + b_out ; 128x64 tile
// ---------------------------------------------------------------------------
__global__ void __launch_bounds__(256) out_gemm_kernel(
    const float* __restrict__ Wout, const float* __restrict__ bout,
    float* __restrict__ out)
{
    constexpr int N = DIM, K = DIM;
    __shared__ float As[16][132];
    __shared__ float Bs[16][64];

    const int tid = threadIdx.x;
    const int tx = tid & 15, ty = tid >> 4;
    const int m0 = blockIdx.x * 128;
    const int n0 = blockIdx.y * 64;

    const int ar  = tid >> 2;
    const int ac4 = (tid & 3) * 4;
    const int br  = tid >> 4;
    const int bc4 = (tid & 15) * 4;

    float acc[8][4] = {};

    for (int k0 = 0; k0 < K; k0 += 16) {
        float4 a0 = *reinterpret_cast<const float4*>(
            &g_att[(size_t)(m0 + ar) * K + k0 + ac4]);
        float4 a1 = *reinterpret_cast<const float4*>(
            &g_att[(size_t)(m0 + ar + 64) * K + k0 + ac4]);
        As[ac4 + 0][ar] = a0.x; As[ac4 + 1][ar] = a0.y;
        As[ac4 + 2][ar] = a0.z; As[ac4 + 3][ar] = a0.w;
        As[ac4 + 0][ar + 64] = a1.x; As[ac4 + 1][ar + 64] = a1.y;
        As[ac4 + 2][ar + 64] = a1.z; As[ac4 + 3][ar + 64] = a1.w;
        *reinterpret_cast<float4*>(&Bs[br][bc4]) =
            *reinterpret_cast<const float4*>(&Wout[(size_t)(k0 + br) * N + n0 + bc4]);
        __syncthreads();
        #pragma unroll
        for (int k = 0; k < 16; k++) {
            float4 a04 = *reinterpret_cast<float4*>(&As[k][ty * 8]);
            float4 a14 = *reinterpret_cast<float4*>(&As[k][ty * 8 + 4]);
            float4 b4  = *reinterpret_cast<float4*>(&Bs[k][tx * 4]);
            float am[8] = {a04.x, a04.y, a04.z, a04.w, a14.x, a14.y, a14.z, a14.w};
            float bn[4] = {b4.x, b4.y, b4.z, b4.w};
            #pragma unroll
            for (int i = 0; i < 8; i++)
                #pragma unroll
                for (int j = 0; j < 4; j++)
                    acc[i][j] += am[i] * bn[j];
        }
        __syncthreads();
    }

    const int n = n0 + tx * 4;
    float4 bb = *reinterpret_cast<const float4*>(&bout[n]);
    #pragma unroll
    for (int i = 0; i < 8; i++) {
        const int m = m0 + ty * 8 + i;
        float4 v;
        v.x = acc[i][0] + bb.x;
        v.y = acc[i][1] + bb.y;
        v.z = acc[i][2] + bb.z;
        v.w = acc[i][3] + bb.w;
        *reinterpret_cast<float4*>(&out[(size_t)m * N + n]) = v;
    }
}

// ---------------------------------------------------------------------------
extern "C" void kernel_launch(void* const* d_in, const int* in_sizes, int n_in,
                              void* d_out, int out_size)
{
    const float* x    = (const float*)d_in[0];
    const float* mask = (const float*)d_in[1];
    const float* Wqkv = (const float*)d_in[2];
    const float* bqkv = (const float*)d_in[3];
    const float* Wout = (const float*)d_in[4];
    const float* bout = (const float*)d_in[5];
    const float* bias = (const float*)d_in[6];
    float* out = (float*)d_out;

    bias_pre_kernel<<<(NSUB * NHEAD * TOK * TOK) / 256, 256>>>(bias);

    qkv_gemm_kernel<<<dim3(1080, 9), 256>>>(x, Wqkv, bqkv);

    const size_t shmem = (size_t)(3 * TOK * 36 + TOK * 148) * sizeof(float);
    static bool attr_set = false;
    if (!attr_set) {
        cudaFuncSetAttribute(attn_kernel,
                             cudaFuncAttributeMaxDynamicSharedMemorySize, (int)shmem);
        attr_set = true;
    }
    attn_kernel<<<dim3(NHEAD, NWIN), 256, shmem>>>(mask);

    out_gemm_kernel<<<dim3(1080, 3), 256>>>(Wout, bout, out);
}

// round 5
// speedup vs baseline: 1.7615x; 1.0524x over previous
#include <cuda_runtime.h>
#include <cstdint>

// ---------------------------------------------------------------------------
// EarthAttention3D with tf32 tensor-core matmuls (mma.sync.m16n8k8)
// ---------------------------------------------------------------------------

constexpr int TOK   = 144;
constexpr int NHEAD = 6;
constexpr int HD    = 32;
constexpr int DIM   = 192;
constexpr int NWIN  = 960;
constexpr int NWW   = 15;
constexpr int NSUB  = 60;
constexpr float QSCALE = 0.17677669529663687f;

__device__ float g_qkv[(size_t)NWIN * 3 * NHEAD * TOK * HD];   // [b][s][h][t][d]
__device__ float g_att[(size_t)NWIN * TOK * DIM];              // [b][t][h*32+d]
__device__ float g_bias[(size_t)NSUB * NHEAD * TOK * TOK];     // [nsub][h][t][s]

__device__ __forceinline__ uint32_t f2tf(float f) {
    uint32_t u;
    asm("cvt.rna.tf32.f32 %0, %1;" : "=r"(u) : "f"(f));
    return u;
}

// D += A(16x8) * B(8x8), tf32 inputs, f32 accum
__device__ __forceinline__ void mma8(float* c, const uint32_t* a, const uint32_t* b) {
    asm volatile(
        "mma.sync.aligned.m16n8k8.row.col.f32.tf32.tf32.f32 "
        "{%0,%1,%2,%3},{%4,%5,%6,%7},{%8,%9},{%0,%1,%2,%3};\n"
        : "+f"(c[0]), "+f"(c[1]), "+f"(c[2]), "+f"(c[3])
        : "r"(a[0]), "r"(a[1]), "r"(a[2]), "r"(a[3]), "r"(b[0]), "r"(b[1]));
}

// ---------------------------------------------------------------------------
// bias precompute: g_bias[nsub][h][t][s]
// ---------------------------------------------------------------------------
__global__ void __launch_bounds__(256) bias_pre_kernel(
    const float* __restrict__ bias_table)
{
    const int idx = blockIdx.x * 256 + threadIdx.x;
    const int s    = idx % TOK;
    const int t    = (idx / TOK) % TOK;
    const int h    = (idx / (TOK * TOK)) % NHEAD;
    const int nsub = idx / (TOK * TOK * NHEAD);

    const int zt = t / 72, ht = (t % 72) / 12, wt = t % 12;
    const int zs = s / 72, hs = (s % 72) / 12, wd = s % 12;
    const int pos = (zt + zs * 2) * 1584 + (ht - hs + 5) * 144 + (wt + wd * 12);

    g_bias[idx] = bias_table[(size_t)pos * (NSUB * NHEAD) + nsub * NHEAD + h];
}

// ---------------------------------------------------------------------------
// GEMM 1: qkv = x[138240,192] @ Wqkv[192,576] + b ; scatter into g_qkv
// 128x64 tile, BK=32, 8 warps (4x2), warp tile 32x32, tf32 mma
// ---------------------------------------------------------------------------
__global__ void __launch_bounds__(256) qkv_gemm_kernel(
    const float* __restrict__ x, const float* __restrict__ Wqkv,
    const float* __restrict__ bqkv)
{
    constexpr int N = 576, K = DIM;
    __shared__ uint32_t As[128 * 33];   // [m][k] stride 33
    __shared__ uint32_t Bs[64 * 33];    // [n][k] stride 33 (transposed)

    const int tid  = threadIdx.x;
    const int wid  = tid >> 5;
    const int lane = tid & 31;
    const int lr = lane >> 2, lc = lane & 3;
    const int wm = wid >> 1, wn = wid & 1;
    const int m0 = blockIdx.x * 128;
    const int n0 = blockIdx.y * 64;

    float c[2][4][4] = {};

    const int ar = tid >> 3, ac4 = (tid & 7) * 4;   // A: 32 rows/pass, 4 passes
    const int bk = tid >> 4, bn4 = (tid & 15) * 4;  // B: 16 k/pass, 2 passes

    for (int k0 = 0; k0 < K; k0 += 32) {
        #pragma unroll
        for (int p = 0; p < 4; p++) {
            const int row = ar + 32 * p;
            float4 v = *reinterpret_cast<const float4*>(
                &x[(size_t)(m0 + row) * K + k0 + ac4]);
            uint32_t* d = &As[row * 33 + ac4];
            d[0] = f2tf(v.x); d[1] = f2tf(v.y); d[2] = f2tf(v.z); d[3] = f2tf(v.w);
        }
        #pragma unroll
        for (int p = 0; p < 2; p++) {
            const int kk = bk + 16 * p;
            float4 v = *reinterpret_cast<const float4*>(
                &Wqkv[(size_t)(k0 + kk) * N + n0 + bn4]);
            Bs[(bn4 + 0) * 33 + kk] = f2tf(v.x);
            Bs[(bn4 + 1) * 33 + kk] = f2tf(v.y);
            Bs[(bn4 + 2) * 33 + kk] = f2tf(v.z);
            Bs[(bn4 + 3) * 33 + kk] = f2tf(v.w);
        }
        __syncthreads();
        #pragma unroll
        for (int ks = 0; ks < 4; ks++) {
            const int kk = ks * 8;
            uint32_t a[2][4], bf[4][2];
            #pragma unroll
            for (int mt = 0; mt < 2; mt++) {
                const int rb = wm * 32 + mt * 16 + lr;
                a[mt][0] = As[rb * 33 + kk + lc];
                a[mt][1] = As[(rb + 8) * 33 + kk + lc];
                a[mt][2] = As[rb * 33 + kk + 4 + lc];
                a[mt][3] = As[(rb + 8) * 33 + kk + 4 + lc];
            }
            #pragma unroll
            for (int nt = 0; nt < 4; nt++) {
                const int cb = wn * 32 + nt * 8 + lr;
                bf[nt][0] = Bs[cb * 33 + kk + lc];
                bf[nt][1] = Bs[cb * 33 + kk + 4 + lc];
            }
            #pragma unroll
            for (int mt = 0; mt < 2; mt++)
                #pragma unroll
                for (int nt = 0; nt < 4; nt++)
                    mma8(c[mt][nt], a[mt], bf[nt]);
        }
        __syncthreads();
    }

    // epilogue: bias, q-scale, scatter (float2 per fragment row)
    #pragma unroll
    for (int nt = 0; nt < 4; nt++) {
        const int n = n0 + wn * 32 + nt * 8 + 2 * lc;   // even
        const int s = n / DIM;
        const int rem = n % DIM;
        const int h = rem >> 5, d = rem & 31;
        const float b0 = bqkv[n], b1 = bqkv[n + 1];
        const float sc = (s == 0) ? QSCALE : 1.0f;
        #pragma unroll
        for (int mt = 0; mt < 2; mt++) {
            #pragma unroll
            for (int half = 0; half < 2; half++) {
                const int m = m0 + wm * 32 + mt * 16 + lr + half * 8;
                const int b = m / TOK, t = m % TOK;
                float2 o;
                o.x = (c[mt][nt][half * 2 + 0] + b0) * sc;
                o.y = (c[mt][nt][half * 2 + 1] + b1) * sc;
                *reinterpret_cast<float2*>(
                    &g_qkv[((((size_t)b * 3 + s) * NHEAD + h) * TOK + t) * HD + d]) = o;
            }
        }
    }
}

// ---------------------------------------------------------------------------
// Attention: block per (head, window). 288 threads = 9 warps.
// QK^T: 3x3 warp grid, 48x48 warp tiles. softmax warp-per-row (16 rows/warp).
// PV: 9 m-stripes of 16 rows, N=32 (4 tiles), K=144 (18 steps).
// ---------------------------------------------------------------------------
__global__ void __launch_bounds__(288, 1) attn_kernel(const float* __restrict__ mask)
{
    extern __shared__ unsigned char sm8[];
    uint32_t* vs = reinterpret_cast<uint32_t*>(sm8);     // 144*40 (tf32)
    uint32_t* qs = vs + TOK * 40;                        // 144*36
    uint32_t* ks = qs + TOK * 36;                        // 144*36
    float*    Ss = reinterpret_cast<float*>(ks + TOK * 36);  // 144*148
    uint32_t* Sb = reinterpret_cast<uint32_t*>(Ss);
    float*  rinv = Ss + TOK * 148;                       // 144

    const int h = blockIdx.x;
    const int b = blockIdx.y;
    const int tid  = threadIdx.x;
    const int wid  = tid >> 5;
    const int lane = tid & 31;
    const int lr = lane >> 2, lc = lane & 3;

    const float* qg = &g_qkv[(((size_t)b * 3 + 0) * NHEAD + h) * TOK * HD];
    const float* kg = &g_qkv[(((size_t)b * 3 + 1) * NHEAD + h) * TOK * HD];
    const float* vg = &g_qkv[(((size_t)b * 3 + 2) * NHEAD + h) * TOK * HD];

    for (int idx = tid; idx < TOK * 8; idx += 288) {
        const int row = idx >> 3;
        const int c4  = (idx & 7) * 4;
        float4 q = *reinterpret_cast<const float4*>(qg + row * 32 + c4);
        float4 k = *reinterpret_cast<const float4*>(kg + row * 32 + c4);
        float4 v = *reinterpret_cast<const float4*>(vg + row * 32 + c4);
        uint32_t* qp = &qs[row * 36 + c4];
        qp[0] = f2tf(q.x); qp[1] = f2tf(q.y); qp[2] = f2tf(q.z); qp[3] = f2tf(q.w);
        uint32_t* kp = &ks[row * 36 + c4];
        kp[0] = f2tf(k.x); kp[1] = f2tf(k.y); kp[2] = f2tf(k.z); kp[3] = f2tf(k.w);
        uint32_t* vp = &vs[row * 40 + c4];
        vp[0] = f2tf(v.x); vp[1] = f2tf(v.y); vp[2] = f2tf(v.z); vp[3] = f2tf(v.w);
    }
    __syncthreads();

    // ---- S = Q K^T ----
    const int wm = wid / 3, wn = wid % 3;
    float c[3][6][4] = {};
    #pragma unroll
    for (int kst = 0; kst < 4; kst++) {
        const int kk = kst * 8;
        uint32_t a[3][4], bf[6][2];
        #pragma unroll
        for (int mt = 0; mt < 3; mt++) {
            const int rb = wm * 48 + mt * 16 + lr;
            a[mt][0] = qs[rb * 36 + kk + lc];
            a[mt][1] = qs[(rb + 8) * 36 + kk + lc];
            a[mt][2] = qs[rb * 36 + kk + 4 + lc];
            a[mt][3] = qs[(rb + 8) * 36 + kk + 4 + lc];
        }
        #pragma unroll
        for (int nt = 0; nt < 6; nt++) {
            const int cb = wn * 48 + nt * 8 + lr;
            bf[nt][0] = ks[cb * 36 + kk + lc];
            bf[nt][1] = ks[cb * 36 + kk + 4 + lc];
        }
        #pragma unroll
        for (int mt = 0; mt < 3; mt++)
            #pragma unroll
            for (int nt = 0; nt < 6; nt++)
                mma8(c[mt][nt], a[mt], bf[nt]);
    }
    // store raw scores
    #pragma unroll
    for (int mt = 0; mt < 3; mt++) {
        const int r = wm * 48 + mt * 16 + lr;
        #pragma unroll
        for (int nt = 0; nt < 6; nt++) {
            const int cc = wn * 48 + nt * 8 + 2 * lc;
            *reinterpret_cast<float2*>(&Ss[r * 148 + cc]) =
                make_float2(c[mt][nt][0], c[mt][nt][1]);
            *reinterpret_cast<float2*>(&Ss[(r + 8) * 148 + cc]) =
                make_float2(c[mt][nt][2], c[mt][nt][3]);
        }
    }
    __syncthreads();

    // ---- softmax (+bias+mask), warp per row, 16 rows/warp ----
    const int wz = b / 240, ww = b % NWW;
    const int nsub = wz * NWW + ww;
    const float* pb = g_bias + (size_t)(nsub * NHEAD + h) * TOK * TOK;
    const float* mk = mask + (size_t)b * TOK * TOK;

    for (int rr = 0; rr < 16; rr++) {
        const int t = wid * 16 + rr;
        float v[5];
        float mx = -1e30f;
        #pragma unroll
        for (int p = 0; p < 5; p++) {
            const int s = lane + 32 * p;
            if (s < TOK) {
                v[p] = Ss[t * 148 + s] + pb[t * TOK + s] + mk[t * TOK + s];
                mx = fmaxf(mx, v[p]);
            } else v[p] = -1e30f;
        }
        #pragma unroll
        for (int o = 16; o; o >>= 1)
            mx = fmaxf(mx, __shfl_xor_sync(0xffffffffu, mx, o));
        float sum = 0.f;
        #pragma unroll
        for (int p = 0; p < 5; p++) {
            const int s = lane + 32 * p;
            if (s < TOK) {
                float e = __expf(v[p] - mx);
                sum += e;
                Sb[t * 148 + s] = f2tf(e);
            }
        }
        #pragma unroll
        for (int o = 16; o; o >>= 1)
            sum += __shfl_xor_sync(0xffffffffu, sum, o);
        if (lane == 0) rinv[t] = 1.0f / sum;
    }
    __syncthreads();

    // ---- out = P V ----
    float o[4][4] = {};
    for (int kst = 0; kst < 18; kst++) {
        const int kk = kst * 8;
        uint32_t a[4];
        const int rb = wid * 16 + lr;
        a[0] = Sb[rb * 148 + kk + lc];
        a[1] = Sb[(rb + 8) * 148 + kk + lc];
        a[2] = Sb[rb * 148 + kk + 4 + lc];
        a[3] = Sb[(rb + 8) * 148 + kk + 4 + lc];
        #pragma unroll
        for (int nt = 0; nt < 4; nt++) {
            uint32_t bf[2];
            bf[0] = vs[(kk + lc) * 40 + nt * 8 + lr];
            bf[1] = vs[(kk + 4 + lc) * 40 + nt * 8 + lr];
            mma8(o[nt], a, bf);
        }
    }
    const float ri0 = rinv[wid * 16 + lr];
    const float ri1 = rinv[wid * 16 + lr + 8];
    float* og = g_att + (size_t)b * TOK * DIM + h * HD;
    #pragma unroll
    for (int nt = 0; nt < 4; nt++) {
        const int cc = nt * 8 + 2 * lc;
        *reinterpret_cast<float2*>(&og[(size_t)(wid * 16 + lr) * DIM + cc]) =
            make_float2(o[nt][0] * ri0, o[nt][1] * ri0);
        *reinterpret_cast<float2*>(&og[(size_t)(wid * 16 + lr + 8) * DIM + cc]) =
            make_float2(o[nt][2] * ri1, o[nt][3] * ri1);
    }
}

// ---------------------------------------------------------------------------
// GEMM 2: out = g_att[138240,192] @ Wout[192,192] + b_out
// ---------------------------------------------------------------------------
__global__ void __launch_bounds__(256) out_gemm_kernel(
    const float* __restrict__ Wout, const float* __restrict__ bout,
    float* __restrict__ out)
{
    constexpr int N = DIM, K = DIM;
    __shared__ uint32_t As[128 * 33];
    __shared__ uint32_t Bs[64 * 33];

    const int tid  = threadIdx.x;
    const int wid  = tid >> 5;
    const int lane = tid & 31;
    const int lr = lane >> 2, lc = lane & 3;
    const int wm = wid >> 1, wn = wid & 1;
    const int m0 = blockIdx.x * 128;
    const int n0 = blockIdx.y * 64;

    float c[2][4][4] = {};

    const int ar = tid >> 3, ac4 = (tid & 7) * 4;
    const int bk = tid >> 4, bn4 = (tid & 15) * 4;

    for (int k0 = 0; k0 < K; k0 += 32) {
        #pragma unroll
        for (int p = 0; p < 4; p++) {
            const int row = ar + 32 * p;
            float4 v = *reinterpret_cast<const float4*>(
                &g_att[(size_t)(m0 + row) * K + k0 + ac4]);
            uint32_t* d = &As[row * 33 + ac4];
            d[0] = f2tf(v.x); d[1] = f2tf(v.y); d[2] = f2tf(v.z); d[3] = f2tf(v.w);
        }
        #pragma unroll
        for (int p = 0; p < 2; p++) {
            const int kk = bk + 16 * p;
            float4 v = *reinterpret_cast<const float4*>(
                &Wout[(size_t)(k0 + kk) * N + n0 + bn4]);
            Bs[(bn4 + 0) * 33 + kk] = f2tf(v.x);
            Bs[(bn4 + 1) * 33 + kk] = f2tf(v.y);
            Bs[(bn4 + 2) * 33 + kk] = f2tf(v.z);
            Bs[(bn4 + 3) * 33 + kk] = f2tf(v.w);
        }
        __syncthreads();
        #pragma unroll
        for (int ks = 0; ks < 4; ks++) {
            const int kk = ks * 8;
            uint32_t a[2][4], bf[4][2];
            #pragma unroll
            for (int mt = 0; mt < 2; mt++) {
                const int rb = wm * 32 + mt * 16 + lr;
                a[mt][0] = As[rb * 33 + kk + lc];
                a[mt][1] = As[(rb + 8) * 33 + kk + lc];
                a[mt][2] = As[rb * 33 + kk + 4 + lc];
                a[mt][3] = As[(rb + 8) * 33 + kk + 4 + lc];
            }
            #pragma unroll
            for (int nt = 0; nt < 4; nt++) {
                const int cb = wn * 32 + nt * 8 + lr;
                bf[nt][0] = Bs[cb * 33 + kk + lc];
                bf[nt][1] = Bs[cb * 33 + kk + 4 + lc];
            }
            #pragma unroll
            for (int mt = 0; mt < 2; mt++)
                #pragma unroll
                for (int nt = 0; nt < 4; nt++)
                    mma8(c[mt][nt], a[mt], bf[nt]);
        }
        __syncthreads();
    }

    #pragma unroll
    for (int nt = 0; nt < 4; nt++) {
        const int n = n0 + wn * 32 + nt * 8 + 2 * lc;
        const float b0 = bout[n], b1 = bout[n + 1];
        #pragma unroll
        for (int mt = 0; mt < 2; mt++) {
            #pragma unroll
            for (int half = 0; half < 2; half++) {
                const int m = m0 + wm * 32 + mt * 16 + lr + half * 8;
                float2 o;
                o.x = c[mt][nt][half * 2 + 0] + b0;
                o.y = c[mt][nt][half * 2 + 1] + b1;
                *reinterpret_cast<float2*>(&out[(size_t)m * N + n]) = o;
            }
        }
    }
}

// ---------------------------------------------------------------------------
extern "C" void kernel_launch(void* const* d_in, const int* in_sizes, int n_in,
                              void* d_out, int out_size)
{
    const float* x    = (const float*)d_in[0];
    const float* mask = (const float*)d_in[1];
    const float* Wqkv = (const float*)d_in[2];
    const float* bqkv = (const float*)d_in[3];
    const float* Wout = (const float*)d_in[4];
    const float* bout = (const float*)d_in[5];
    const float* bias = (const float*)d_in[6];
    float* out = (float*)d_out;

    bias_pre_kernel<<<(NSUB * NHEAD * TOK * TOK) / 256, 256>>>(bias);

    qkv_gemm_kernel<<<dim3(1080, 9), 256>>>(x, Wqkv, bqkv);

    const size_t shmem = (size_t)(TOK * 40 + 2 * TOK * 36 + TOK * 148 + TOK)
                         * sizeof(float);
    cudaFuncSetAttribute(attn_kernel,
                         cudaFuncAttributeMaxDynamicSharedMemorySize, (int)shmem);
    attn_kernel<<<dim3(NHEAD, NWIN), 288, shmem>>>(mask);

    out_gemm_kernel<<<dim3(1080, 3), 256>>>(Wout, bout, out);
}